// round 2
// baseline (speedup 1.0000x reference)
#include <cuda_runtime.h>
#include <cstdint>

// ---------------- problem constants ----------------
#define NTOT 10647          // 3*(13*13 + 26*26 + 52*52)
#define KNMS 100
#define BMAX 32
#define NCLS 80
#define IOU_THR 0.3f

// ---------------- device scratch (no allocations allowed) ----------------
__device__ float g_boxes[(size_t)BMAX * NTOT * 6];   // [B, NTOT, 6]
__device__ float g_scores[(size_t)BMAX * NTOT];      // [B, NTOT] (0 if conf<=thresh)

__device__ __forceinline__ float sigmoidf_(float x) {
    return 1.0f / (1.0f + expf(-x));
}

// ============================================================
// Kernel 1: decode one YOLO scale.
// input: [B, 3*85, S, S]; thread = (b, anchor a, cell y, x).
// Channel loop -> coalesced loads (x is fastest dim across threads).
// ============================================================
__global__ void __launch_bounds__(256)
decode_kernel(const float* __restrict__ in,
              const float* __restrict__ anc,   // 3x2 for this scale
              const float* __restrict__ thr_p, // scalar on device
              int S, float stride, int B, int outBase)
{
    int tid = blockIdx.x * blockDim.x + threadIdx.x;
    int cs = S * S;
    int per = 3 * cs;
    int total = B * per;
    if (tid >= total) return;

    int b = tid / per;
    int r = tid - b * per;
    int a = r / cs;
    int cell = r - a * cs;
    int y = cell / S;
    int x = cell - y * S;

    const float* p = in + ((size_t)b * 255 + (size_t)a * 85) * cs + (size_t)y * S + x;
    float thr = *thr_p;

    float p0 = p[0];
    float conf = sigmoidf_(p0);
    float sx = sigmoidf_(p[(size_t)1 * cs]);
    float sy = sigmoidf_(p[(size_t)2 * cs]);
    float w  = expf(p[(size_t)3 * cs]) * anc[a * 2 + 0];
    float h  = expf(p[(size_t)4 * cs]) * anc[a * 2 + 1];

    // argmax over 80 classes (first max wins, like jnp.argmax)
    int best = 0;
    float bv = p[(size_t)5 * cs];
    #pragma unroll 4
    for (int c = 1; c < NCLS; ++c) {
        float v = p[(size_t)(5 + c) * cs];
        if (v > bv) { bv = v; best = c; }
    }

    float ox = ((float)x + sx) * stride;
    float oy = ((float)y + sy) * stride;

    int n = outBase + (y * S + x) * 3 + a;
    float* ob = g_boxes + ((size_t)b * NTOT + n) * 6;
    ob[0] = ox - 0.5f * w;
    ob[1] = oy - 0.5f * h;
    ob[2] = ox + 0.5f * w;
    ob[3] = oy + 0.5f * h;
    ob[4] = (float)best;
    ob[5] = conf;

    g_scores[(size_t)b * NTOT + n] = (conf > thr) ? conf : 0.0f;
}

// ============================================================
// Kernel 2: per-image exact top-100 (radix-select on float bits,
// stable ties by smallest index) + bitonic sort + greedy NMS.
// One block per image, 256 threads.
// ============================================================
__global__ void __launch_bounds__(256)
topk_nms_kernel(float* __restrict__ out, int B)
{
    const int b = blockIdx.x;
    const int tid = threadIdx.x;
    const float* s = g_scores + (size_t)b * NTOT;

    __shared__ unsigned hist[256];
    __shared__ unsigned sh_prefix;
    __shared__ int sh_k;
    __shared__ int sh_cnt, sh_min, sh_last;
    __shared__ unsigned long long keys[128];
    __shared__ float sb[KNMS * 6];
    __shared__ float sarea[KNMS];
    __shared__ int skeep[KNMS];

    if (tid == 0) { sh_prefix = 0u; sh_k = KNMS; }
    __syncthreads();

    // ---- 4-pass radix select (scores >= 0 -> uint bits order-preserving) ----
    for (int pass = 0; pass < 4; ++pass) {
        unsigned prefix = sh_prefix;
        int shift = 24 - 8 * pass;
        unsigned maskHigh = (pass == 0) ? 0u : (0xFFFFFFFFu << (shift + 8));
        hist[tid] = 0u;
        __syncthreads();
        for (int n = tid; n < NTOT; n += 256) {
            unsigned bits = __float_as_uint(s[n]);
            if ((bits & maskHigh) == prefix)
                atomicAdd(&hist[(bits >> shift) & 0xFF], 1u);
        }
        __syncthreads();
        if (tid == 0) {
            int k = sh_k;
            for (int bin = 255; bin >= 0; --bin) {
                int c = (int)hist[bin];
                if (c >= k) {
                    sh_prefix = prefix | ((unsigned)bin << shift);
                    sh_k = k;
                    break;
                }
                k -= c;
            }
        }
        __syncthreads();
    }

    const unsigned Tbits = sh_prefix;   // bits of the 100th-largest score
    const int k_eq = sh_k;              // how many ==T entries we still need

    // ---- collect strictly-greater elements (unordered) ----
    if (tid == 0) sh_cnt = 0;
    __syncthreads();
    for (int n = tid; n < NTOT; n += 256) {
        unsigned bits = __float_as_uint(s[n]);
        if (bits > Tbits) {
            int pos = atomicAdd(&sh_cnt, 1);
            keys[pos] = ((unsigned long long)bits << 32) | (unsigned)(~(unsigned)n);
        }
    }
    __syncthreads();
    const int cnt_gt = sh_cnt;          // == KNMS - k_eq

    // ---- append k_eq smallest-index elements equal to T (stable tie-break) ----
    if (tid == 0) sh_last = -1;
    __syncthreads();
    for (int it = 0; it < k_eq; ++it) {
        if (tid == 0) sh_min = 0x7FFFFFFF;
        __syncthreads();
        int last = sh_last;
        for (int n = tid; n < NTOT; n += 256) {
            if (__float_as_uint(s[n]) == Tbits && n > last)
                atomicMin(&sh_min, n);
        }
        __syncthreads();
        if (tid == 0) {
            keys[cnt_gt + it] =
                ((unsigned long long)Tbits << 32) | (unsigned)(~(unsigned)sh_min);
            sh_last = sh_min;
        }
        __syncthreads();
    }

    if (tid >= KNMS && tid < 128) keys[tid] = 0ull;  // pad for bitonic
    __syncthreads();

    // ---- bitonic sort, 128 wide, DESCENDING (score desc, index asc) ----
    for (int size = 2; size <= 128; size <<= 1) {
        for (int stride = size >> 1; stride > 0; stride >>= 1) {
            __syncthreads();
            if (tid < 128) {
                int partner = tid ^ stride;
                if (partner > tid) {
                    bool asc = ((tid & size) != 0);   // mirrored net -> descending
                    unsigned long long a = keys[tid], bb = keys[partner];
                    bool swap = asc ? (a > bb) : (a < bb);
                    if (swap) { keys[tid] = bb; keys[partner] = a; }
                }
            }
        }
    }
    __syncthreads();

    // ---- gather selected boxes into shared; keep0 = (score > 0) <=> conf > thresh ----
    if (tid < KNMS) {
        unsigned long long key = keys[tid];
        unsigned idx = ~(unsigned)(key & 0xFFFFFFFFu);
        float sc = __uint_as_float((unsigned)(key >> 32));
        const float* ob = g_boxes + ((size_t)b * NTOT + idx) * 6;
        #pragma unroll
        for (int c = 0; c < 6; ++c) sb[tid * 6 + c] = ob[c];
        skeep[tid] = (sc > 0.0f) ? 1 : 0;
        sarea[tid] = fmaxf(sb[tid * 6 + 2] - sb[tid * 6 + 0], 0.0f) *
                     fmaxf(sb[tid * 6 + 3] - sb[tid * 6 + 1], 0.0f);
    }
    __syncthreads();

    // ---- greedy per-class NMS ----
    for (int i = 0; i < KNMS - 1; ++i) {
        __syncthreads();
        if (skeep[i]) {
            int j = tid;
            if (j > i && j < KNMS && skeep[j] && sb[j * 6 + 4] == sb[i * 6 + 4]) {
                float x1 = fmaxf(sb[i * 6 + 0], sb[j * 6 + 0]);
                float y1 = fmaxf(sb[i * 6 + 1], sb[j * 6 + 1]);
                float x2 = fminf(sb[i * 6 + 2], sb[j * 6 + 2]);
                float y2 = fminf(sb[i * 6 + 3], sb[j * 6 + 3]);
                float inter = fmaxf(x2 - x1, 0.0f) * fmaxf(y2 - y1, 0.0f);
                float uni = sarea[i] + sarea[j] - inter;
                float iou = inter / fmaxf(uni, 1e-9f);
                if (iou > IOU_THR) skeep[j] = 0;
            }
        }
    }
    __syncthreads();

    // ---- write: sel [B,100,6] then keep [B,100] as 0/1 float ----
    float* out_sel = out;
    float* out_keep = out + (size_t)B * KNMS * 6;
    if (tid < KNMS) {
        #pragma unroll
        for (int c = 0; c < 6; ++c)
            out_sel[((size_t)b * KNMS + tid) * 6 + c] = sb[tid * 6 + c];
        out_keep[(size_t)b * KNMS + tid] = skeep[tid] ? 1.0f : 0.0f;
    }
}

// ============================================================
extern "C" void kernel_launch(void* const* d_in, const int* in_sizes, int n_in,
                              void* d_out, int out_size)
{
    const float* o13 = (const float*)d_in[0];
    const float* o26 = (const float*)d_in[1];
    const float* o52 = (const float*)d_in[2];
    const float* anc = (const float*)d_in[3];   // [3,3,2]
    const float* thr = (const float*)d_in[4];   // scalar

    int B = in_sizes[0] / (255 * 13 * 13);
    if (B > BMAX) B = BMAX;
    float* out = (float*)d_out;

    const int TPB = 256;
    int t13 = B * 3 * 13 * 13;
    int t26 = B * 3 * 26 * 26;
    int t52 = B * 3 * 52 * 52;

    decode_kernel<<<(t13 + TPB - 1) / TPB, TPB>>>(o13, anc + 0,  thr, 13, 32.0f, B, 0);
    decode_kernel<<<(t26 + TPB - 1) / TPB, TPB>>>(o26, anc + 6,  thr, 26, 16.0f, B, 507);
    decode_kernel<<<(t52 + TPB - 1) / TPB, TPB>>>(o52, anc + 12, thr, 52, 8.0f,  B, 2535);

    topk_nms_kernel<<<B, TPB>>>(out, B);
}

// round 4
// speedup vs baseline: 2.1587x; 2.1587x over previous
#include <cuda_runtime.h>
#include <cstdint>

// ---------------- problem constants ----------------
#define NTOT 10647          // 3*(13*13 + 26*26 + 52*52)
#define KNMS 100
#define BMAX 32
#define NCLS 80
#define IOU_THR 0.3f

#define CS13 169
#define CS26 676
#define CS52 2704
#define BASE13 0
#define BASE26 507
#define BASE52 2535

__device__ __forceinline__ float sigmoidf_(float x) {
    return 1.0f / (1.0f + expf(-x));
}

// ============================================================
// One block per image, 1024 threads. Does EVERYTHING:
//  1. score (sigmoid of objectness channel only) -> shared
//  2. exact top-100 via shared-memory radix select (stable ties)
//  3. bitonic sort (score desc, index asc)
//  4. gather-decode only the 100 selected anchors (1 warp/box)
//  5. greedy per-class NMS in shared
// ============================================================
__global__ void __launch_bounds__(1024)
detector_kernel(const float* __restrict__ o13, const float* __restrict__ o26,
                const float* __restrict__ o52, const float* __restrict__ anc,
                const float* __restrict__ thr_p,
                float* __restrict__ out, int B)
{
    const int b = blockIdx.x;
    const int tid = threadIdx.x;

    __shared__ float s_scores[NTOT];                 // 42588 B
    __shared__ unsigned hist[256];                   // 1024 B
    __shared__ unsigned long long keys[128];         // 1024 B (aliased as suf[256])
    __shared__ float sb[KNMS * 6];                   // 2400 B
    __shared__ float sarea[KNMS];                    // 400 B
    __shared__ int skeep[KNMS];                      // 400 B
    __shared__ unsigned sh_prefix;
    __shared__ int sh_k, sh_cnt, sh_min, sh_last;

    const float thr = *thr_p;

    // ---- 1. score pass: conf channel (a*85) of each anchor, coalesced ----
    {
        const float* base13 = o13 + (size_t)b * 255 * CS13;
        const float* base26 = o26 + (size_t)b * 255 * CS26;
        const float* base52 = o52 + (size_t)b * 255 * CS52;
        #pragma unroll
        for (int a = 0; a < 3; ++a) {
            const float* p13 = base13 + (size_t)a * 85 * CS13;
            const float* p26 = base26 + (size_t)a * 85 * CS26;
            const float* p52 = base52 + (size_t)a * 85 * CS52;
            for (int cell = tid; cell < CS13; cell += 1024) {
                float c = sigmoidf_(p13[cell]);
                s_scores[BASE13 + cell * 3 + a] = (c > thr) ? c : 0.0f;
            }
            for (int cell = tid; cell < CS26; cell += 1024) {
                float c = sigmoidf_(p26[cell]);
                s_scores[BASE26 + cell * 3 + a] = (c > thr) ? c : 0.0f;
            }
            for (int cell = tid; cell < CS52; cell += 1024) {
                float c = sigmoidf_(p52[cell]);
                s_scores[BASE52 + cell * 3 + a] = (c > thr) ? c : 0.0f;
            }
        }
    }
    if (tid == 0) { sh_prefix = 0u; sh_k = KNMS; }
    __syncthreads();

    // ---- 2. 4-pass radix select on float bits (all scores >= 0) ----
    unsigned* suf = (unsigned*)keys;                 // keys not used yet
    for (int pass = 0; pass < 4; ++pass) {
        unsigned prefix = sh_prefix;
        int k = sh_k;
        int shift = 24 - 8 * pass;
        unsigned maskHigh = (pass == 0) ? 0u : (0xFFFFFFFFu << (shift + 8));
        if (tid < 256) hist[tid] = 0u;
        __syncthreads();
        for (int n = tid; n < NTOT; n += 1024) {
            unsigned bits = __float_as_uint(s_scores[n]);
            if ((bits & maskHigh) == prefix)
                atomicAdd(&hist[(bits >> shift) & 0xFF], 1u);
        }
        __syncthreads();
        // parallel suffix-sum over 256 bins
        if (tid < 256) suf[tid] = hist[tid];
        __syncthreads();
        for (int off = 1; off < 256; off <<= 1) {
            unsigned v = 0;
            if (tid < 256 && tid + off < 256) v = suf[tid + off];
            __syncthreads();
            if (tid < 256) suf[tid] += v;
            __syncthreads();
        }
        // largest bin whose suffix-count >= k
        if (tid < 256) {
            unsigned S = suf[tid];
            unsigned Sn = (tid < 255) ? suf[tid + 1] : 0u;
            if ((int)S >= k && (int)Sn < k) {
                sh_prefix = prefix | ((unsigned)tid << shift);
                sh_k = k - (int)Sn;
            }
        }
        __syncthreads();
    }

    const unsigned Tbits = sh_prefix;   // bits of 100th-largest score
    const int k_eq = sh_k;              // # of ==T entries still needed

    // ---- collect strictly-greater (unordered) ----
    if (tid == 0) sh_cnt = 0;
    __syncthreads();
    for (int n = tid; n < NTOT; n += 1024) {
        unsigned bits = __float_as_uint(s_scores[n]);
        if (bits > Tbits) {
            int pos = atomicAdd(&sh_cnt, 1);
            keys[pos] = ((unsigned long long)bits << 32) | (unsigned)(~(unsigned)n);
        }
    }
    __syncthreads();
    const int cnt_gt = sh_cnt;

    // ---- append k_eq smallest-index ==T elements (stable tie-break) ----
    if (tid == 0) sh_last = -1;
    __syncthreads();
    for (int it = 0; it < k_eq; ++it) {
        if (tid == 0) sh_min = 0x7FFFFFFF;
        __syncthreads();
        int last = sh_last;
        for (int n = tid; n < NTOT; n += 1024) {
            if (__float_as_uint(s_scores[n]) == Tbits && n > last)
                atomicMin(&sh_min, n);
        }
        __syncthreads();
        if (tid == 0) {
            keys[cnt_gt + it] =
                ((unsigned long long)Tbits << 32) | (unsigned)(~(unsigned)sh_min);
            sh_last = sh_min;
        }
        __syncthreads();
    }
    if (tid >= KNMS && tid < 128) keys[tid] = 0ull;
    __syncthreads();

    // ---- 3. bitonic sort 128 wide, descending (score desc, idx asc) ----
    for (int size = 2; size <= 128; size <<= 1) {
        for (int stride = size >> 1; stride > 0; stride >>= 1) {
            __syncthreads();
            if (tid < 128) {
                int partner = tid ^ stride;
                if (partner > tid) {
                    bool asc = ((tid & size) != 0);
                    unsigned long long a = keys[tid], bb = keys[partner];
                    bool sw = asc ? (a > bb) : (a < bb);
                    if (sw) { keys[tid] = bb; keys[partner] = a; }
                }
            }
        }
    }
    __syncthreads();

    // ---- 4. gather + decode the 100 selected anchors (1 warp / box) ----
    {
        int wid = tid >> 5, lane = tid & 31;
        for (int box = wid; box < KNMS; box += 32) {
            unsigned long long key = keys[box];
            unsigned idx = ~(unsigned)(key & 0xFFFFFFFFu);

            int S, cs, base; float strd; const float* in; const float* arow;
            if (idx < BASE26)      { S = 13; cs = CS13; base = BASE13; strd = 32.f; in = o13; arow = anc + 0; }
            else if (idx < BASE52) { S = 26; cs = CS26; base = BASE26; strd = 16.f; in = o26; arow = anc + 6; }
            else                   { S = 52; cs = CS52; base = BASE52; strd = 8.f;  in = o52; arow = anc + 12; }
            int m = (int)idx - base;
            int cell = m / 3, a = m - cell * 3;
            int y = cell / S, x = cell - y * S;
            const float* p = in + ((size_t)b * 255 + (size_t)a * 85) * cs + cell;

            // lanes load channels lane, lane+32, lane+64
            float v0 = p[(size_t)lane * cs];                          // ch 0..31
            float v1 = p[(size_t)(lane + 32) * cs];                   // ch 32..63
            float v2 = (lane < 21) ? p[(size_t)(lane + 64) * cs] : 0.f; // ch 64..84

            float ch0 = __shfl_sync(0xffffffffu, v0, 0);
            float ch1 = __shfl_sync(0xffffffffu, v0, 1);
            float ch2 = __shfl_sync(0xffffffffu, v0, 2);
            float ch3 = __shfl_sync(0xffffffffu, v0, 3);
            float ch4 = __shfl_sync(0xffffffffu, v0, 4);

            // per-lane class best (ch>=5 -> class = ch-5), first-max wins
            float bv = -3.402823466e+38f;
            int bi = 0x7FFFFFFF;
            if (lane >= 5)            { bv = v0; bi = lane - 5; }
            if (v1 > bv)              { bv = v1; bi = lane + 27; }
            if (lane < 21 && v2 > bv) { bv = v2; bi = lane + 59; }
            #pragma unroll
            for (int off = 16; off; off >>= 1) {
                float ov = __shfl_xor_sync(0xffffffffu, bv, off);
                int oi = __shfl_xor_sync(0xffffffffu, bi, off);
                if (ov > bv || (ov == bv && oi < bi)) { bv = ov; bi = oi; }
            }

            if (lane == 0) {
                float conf = sigmoidf_(ch0);
                float sx = sigmoidf_(ch1);
                float sy = sigmoidf_(ch2);
                float ww = expf(ch3) * arow[a * 2 + 0];
                float hh = expf(ch4) * arow[a * 2 + 1];
                float ox = ((float)x + sx) * strd;
                float oy = ((float)y + sy) * strd;
                float x1 = ox - 0.5f * ww, y1 = oy - 0.5f * hh;
                float x2 = ox + 0.5f * ww, y2 = oy + 0.5f * hh;
                sb[box * 6 + 0] = x1;
                sb[box * 6 + 1] = y1;
                sb[box * 6 + 2] = x2;
                sb[box * 6 + 3] = y2;
                sb[box * 6 + 4] = (float)bi;
                sb[box * 6 + 5] = conf;
                sarea[box] = fmaxf(x2 - x1, 0.f) * fmaxf(y2 - y1, 0.f);
                skeep[box] = (conf > thr) ? 1 : 0;
            }
        }
    }
    __syncthreads();

    // ---- 5. greedy per-class NMS ----
    for (int i = 0; i < KNMS - 1; ++i) {
        __syncthreads();
        if (skeep[i]) {
            int j = tid;
            if (j > i && j < KNMS && skeep[j] && sb[j * 6 + 4] == sb[i * 6 + 4]) {
                float x1 = fmaxf(sb[i * 6 + 0], sb[j * 6 + 0]);
                float y1 = fmaxf(sb[i * 6 + 1], sb[j * 6 + 1]);
                float x2 = fminf(sb[i * 6 + 2], sb[j * 6 + 2]);
                float y2 = fminf(sb[i * 6 + 3], sb[j * 6 + 3]);
                float inter = fmaxf(x2 - x1, 0.0f) * fmaxf(y2 - y1, 0.0f);
                float uni = sarea[i] + sarea[j] - inter;
                float iou = inter / fmaxf(uni, 1e-9f);
                if (iou > IOU_THR) skeep[j] = 0;
            }
        }
    }
    __syncthreads();

    // ---- write: sel [B,100,6] then keep [B,100] as 0/1 float ----
    float* out_sel = out;
    float* out_keep = out + (size_t)B * KNMS * 6;
    if (tid < KNMS) {
        #pragma unroll
        for (int c = 0; c < 6; ++c)
            out_sel[((size_t)b * KNMS + tid) * 6 + c] = sb[tid * 6 + c];
        out_keep[(size_t)b * KNMS + tid] = skeep[tid] ? 1.0f : 0.0f;
    }
}

// ============================================================
extern "C" void kernel_launch(void* const* d_in, const int* in_sizes, int n_in,
                              void* d_out, int out_size)
{
    const float* o13 = (const float*)d_in[0];
    const float* o26 = (const float*)d_in[1];
    const float* o52 = (const float*)d_in[2];
    const float* anc = (const float*)d_in[3];   // [3,3,2]
    const float* thr = (const float*)d_in[4];   // scalar

    int B = in_sizes[0] / (255 * CS13);
    if (B > BMAX) B = BMAX;
    float* out = (float*)d_out;

    detector_kernel<<<B, 1024>>>(o13, o26, o52, anc, thr, out, B);
}

// round 6
// speedup vs baseline: 2.4528x; 1.1363x over previous
#include <cuda_runtime.h>
#include <cstdint>

// ---------------- problem constants ----------------
#define NTOT 10647          // 3*(13*13 + 26*26 + 52*52)
#define KNMS 100
#define BMAX 32
#define IOU_THR 0.3f

#define CS13 169
#define CS26 676
#define CS52 2704
#define BASE13 0
#define BASE26 507
#define BASE52 2535

// ---------------- device scratch ----------------
__device__ unsigned long long g_keys[BMAX * 128];  // per image: 100 keys + 28 zero pad
__device__ float g_dec[BMAX * KNMS * 6];           // decoded boxes, slot order

__device__ __forceinline__ float sigmoidf_(float x) {
    return 1.0f / (1.0f + expf(-x));
}

// ============================================================
// Kernel A: one block/image, 1024 threads.
//  score (conf channel only) -> shared; exact top-100 via radix
//  select (warp-aggregated histogram, warp-shuffle bin pick);
//  gather-decode the 100 selected anchors (1 warp/box, unsorted).
// ============================================================
__global__ void __launch_bounds__(1024)
stageA_kernel(const float* __restrict__ o13, const float* __restrict__ o26,
              const float* __restrict__ o52, const float* __restrict__ anc,
              const float* __restrict__ thr_p, int B)
{
    const int b = blockIdx.x;
    const int tid = threadIdx.x;
    const int lane = tid & 31;

    __shared__ float s_scores[NTOT];                 // 42588 B
    __shared__ unsigned hist[256];
    __shared__ unsigned long long s_keys[128];
    __shared__ unsigned sh_prefix;
    __shared__ int sh_k, sh_cnt, sh_min, sh_last;

    const float thr = *thr_p;

    // ---- score pass: conf channel (a*85) of each anchor, coalesced ----
    {
        const float* base13 = o13 + (size_t)b * 255 * CS13;
        const float* base26 = o26 + (size_t)b * 255 * CS26;
        const float* base52 = o52 + (size_t)b * 255 * CS52;
        #pragma unroll
        for (int a = 0; a < 3; ++a) {
            const float* p13 = base13 + (size_t)a * 85 * CS13;
            const float* p26 = base26 + (size_t)a * 85 * CS26;
            const float* p52 = base52 + (size_t)a * 85 * CS52;
            for (int cell = tid; cell < CS13; cell += 1024) {
                float c = sigmoidf_(p13[cell]);
                s_scores[BASE13 + cell * 3 + a] = (c > thr) ? c : 0.0f;
            }
            for (int cell = tid; cell < CS26; cell += 1024) {
                float c = sigmoidf_(p26[cell]);
                s_scores[BASE26 + cell * 3 + a] = (c > thr) ? c : 0.0f;
            }
            for (int cell = tid; cell < CS52; cell += 1024) {
                float c = sigmoidf_(p52[cell]);
                s_scores[BASE52 + cell * 3 + a] = (c > thr) ? c : 0.0f;
            }
        }
    }
    if (tid == 0) { sh_prefix = 0u; sh_k = KNMS; }
    __syncthreads();

    // ---- 4-pass radix select on float bits (all scores >= 0) ----
    for (int pass = 0; pass < 4; ++pass) {
        unsigned prefix = sh_prefix;
        int k = sh_k;
        int shift = 24 - 8 * pass;
        unsigned maskHigh = (pass == 0) ? 0u : (0xFFFFFFFFu << (shift + 8));
        if (tid < 256) hist[tid] = 0u;
        __syncthreads();

        // histogram with warp-aggregated atomics (match_any)
        for (int base = 0; base < NTOT; base += 1024) {
            int n = base + tid;
            bool inb = (n < NTOT);
            unsigned bits = inb ? __float_as_uint(s_scores[n]) : 0u;
            bool active = inb && ((bits & maskHigh) == prefix);
            unsigned actmask = __ballot_sync(0xffffffffu, active);
            if (active) {
                unsigned bin = (bits >> shift) & 0xFF;
                unsigned peers = __match_any_sync(actmask, bin);
                if (lane == __ffs(peers) - 1)
                    atomicAdd(&hist[bin], (unsigned)__popc(peers));
            }
        }
        __syncthreads();

        // warp 0 picks threshold bin via shuffle suffix-scan (8 bins/lane)
        if (tid < 32) {
            unsigned c[8];
            int T = 0;
            #pragma unroll
            for (int r = 0; r < 8; ++r) { c[r] = hist[tid * 8 + r]; T += (int)c[r]; }
            int S = T;
            #pragma unroll
            for (int off = 1; off < 32; off <<= 1) {
                int v = __shfl_down_sync(0xffffffffu, S, off);
                if (tid + off < 32) S += v;
            }
            int Snext = __shfl_down_sync(0xffffffffu, S, 1);
            if (tid == 31) Snext = 0;
            if (S >= k && Snext < k) {
                int rem = Snext, chosen = 0;
                #pragma unroll
                for (int r = 7; r >= 0; --r) {
                    if (rem + (int)c[r] >= k) { chosen = r; break; }
                    rem += (int)c[r];
                }
                sh_prefix = prefix | ((unsigned)(tid * 8 + chosen) << shift);
                sh_k = k - rem;
            }
        }
        __syncthreads();
    }

    const unsigned Tbits = sh_prefix;   // bits of 100th-largest score
    const int k_eq = sh_k;              // # of ==T entries still needed

    // ---- collect strictly-greater (unordered slots) ----
    if (tid == 0) sh_cnt = 0;
    __syncthreads();
    for (int n = tid; n < NTOT; n += 1024) {
        unsigned bits = __float_as_uint(s_scores[n]);
        if (bits > Tbits) {
            int pos = atomicAdd(&sh_cnt, 1);
            s_keys[pos] = ((unsigned long long)bits << 32) | (unsigned)(~(unsigned)n);
        }
    }
    __syncthreads();
    const int cnt_gt = sh_cnt;

    // ---- append k_eq smallest-index ==T elements (stable tie-break) ----
    if (tid == 0) sh_last = -1;
    __syncthreads();
    for (int it = 0; it < k_eq; ++it) {
        if (tid == 0) sh_min = 0x7FFFFFFF;
        __syncthreads();
        int last = sh_last;
        for (int n = tid; n < NTOT; n += 1024) {
            if (__float_as_uint(s_scores[n]) == Tbits && n > last)
                atomicMin(&sh_min, n);
        }
        __syncthreads();
        if (tid == 0) {
            s_keys[cnt_gt + it] =
                ((unsigned long long)Tbits << 32) | (unsigned)(~(unsigned)sh_min);
            sh_last = sh_min;
        }
        __syncthreads();
    }
    __syncthreads();

    // ---- export keys (100 real + 28 zero pad) ----
    if (tid < 128) g_keys[b * 128 + tid] = (tid < KNMS) ? s_keys[tid] : 0ull;

    // ---- gather + decode the 100 selected anchors (1 warp/box, unsorted) ----
    {
        int wid = tid >> 5;
        for (int box = wid; box < KNMS; box += 32) {
            unsigned long long key = s_keys[box];
            unsigned idx = ~(unsigned)(key & 0xFFFFFFFFu);

            int S, cs, base; float strd; const float* in; const float* arow;
            if (idx < BASE26)      { S = 13; cs = CS13; base = BASE13; strd = 32.f; in = o13; arow = anc + 0; }
            else if (idx < BASE52) { S = 26; cs = CS26; base = BASE26; strd = 16.f; in = o26; arow = anc + 6; }
            else                   { S = 52; cs = CS52; base = BASE52; strd = 8.f;  in = o52; arow = anc + 12; }
            int m = (int)idx - base;
            int cell = m / 3, a = m - cell * 3;
            int y = cell / S, x = cell - y * S;
            const float* p = in + ((size_t)b * 255 + (size_t)a * 85) * cs + cell;

            float v0 = p[(size_t)lane * cs];                            // ch 0..31
            float v1 = p[(size_t)(lane + 32) * cs];                     // ch 32..63
            float v2 = (lane < 21) ? p[(size_t)(lane + 64) * cs] : 0.f; // ch 64..84

            float ch0 = __shfl_sync(0xffffffffu, v0, 0);
            float ch1 = __shfl_sync(0xffffffffu, v0, 1);
            float ch2 = __shfl_sync(0xffffffffu, v0, 2);
            float ch3 = __shfl_sync(0xffffffffu, v0, 3);
            float ch4 = __shfl_sync(0xffffffffu, v0, 4);

            // class argmax (ch>=5 -> class ch-5), first-max wins
            float bv = -3.402823466e+38f;
            int bi = 0x7FFFFFFF;
            if (lane >= 5)            { bv = v0; bi = lane - 5; }
            if (v1 > bv)              { bv = v1; bi = lane + 27; }
            if (lane < 21 && v2 > bv) { bv = v2; bi = lane + 59; }
            #pragma unroll
            for (int off = 16; off; off >>= 1) {
                float ov = __shfl_xor_sync(0xffffffffu, bv, off);
                int oi = __shfl_xor_sync(0xffffffffu, bi, off);
                if (ov > bv || (ov == bv && oi < bi)) { bv = ov; bi = oi; }
            }

            if (lane == 0) {
                float conf = sigmoidf_(ch0);
                float sx = sigmoidf_(ch1);
                float sy = sigmoidf_(ch2);
                float ww = expf(ch3) * arow[a * 2 + 0];
                float hh = expf(ch4) * arow[a * 2 + 1];
                float ox = ((float)x + sx) * strd;
                float oy = ((float)y + sy) * strd;
                float* d = g_dec + ((size_t)b * KNMS + box) * 6;
                d[0] = ox - 0.5f * ww;
                d[1] = oy - 0.5f * hh;
                d[2] = ox + 0.5f * ww;
                d[3] = oy + 0.5f * hh;
                d[4] = (float)bi;
                d[5] = conf;
            }
        }
    }
}

// ============================================================
// Kernel B: one block/image, 256 threads.
//  sort 128 keys (shared bitonic w/ slot payload), gather boxes,
//  parallel suppression-bitmask build, single-thread exact greedy,
//  write sel + keep.
// ============================================================
__global__ void __launch_bounds__(256)
stageB_kernel(float* __restrict__ out, int B)
{
    const int b = blockIdx.x;
    const int t = threadIdx.x;

    __shared__ unsigned long long skey[128];
    __shared__ int spay[128];
    __shared__ float sbox[KNMS][6];
    __shared__ float sarea[KNMS];
    __shared__ unsigned sup[KNMS][4];
    __shared__ unsigned keep0w[4];
    __shared__ unsigned keepw[4];

    if (t < 128) { skey[t] = g_keys[b * 128 + t]; spay[t] = t; }
    __syncthreads();

    // bitonic sort 128 desc (score desc, anchor idx asc), payload = slot
    for (int size = 2; size <= 128; size <<= 1) {
        for (int stride = size >> 1; stride > 0; stride >>= 1) {
            __syncthreads();
            if (t < 128) {
                int partner = t ^ stride;
                if (partner > t) {
                    bool asc = ((t & size) != 0);
                    unsigned long long a = skey[t], bb = skey[partner];
                    bool sw = asc ? (a > bb) : (a < bb);
                    if (sw) {
                        skey[t] = bb; skey[partner] = a;
                        int pa = spay[t]; spay[t] = spay[partner]; spay[partner] = pa;
                    }
                }
            }
        }
    }
    __syncthreads();

    // gather boxes in sorted order; valid = score bits > 0
    bool valid = false;
    if (t < KNMS) {
        int slot = spay[t];
        const float* d = g_dec + ((size_t)b * KNMS + slot) * 6;
        #pragma unroll
        for (int c = 0; c < 6; ++c) sbox[t][c] = d[c];
        sarea[t] = fmaxf(sbox[t][2] - sbox[t][0], 0.f) *
                   fmaxf(sbox[t][3] - sbox[t][1], 0.f);
        valid = ((unsigned)(skey[t] >> 32)) != 0u;
    }
    // keep0 ballot (warps 0..3 cover t<128)
    if (t < 128) {
        unsigned bal = __ballot_sync(0xffffffffu, valid);
        if ((t & 31) == 0) keep0w[t >> 5] = bal;
    }
    __syncthreads();

    // suppression masks: sup[i][c] bit (j-32c) set if i suppresses j (j>i)
    for (int w = t; w < KNMS * 4; w += 256) {
        int i = w >> 2, c = w & 3;
        unsigned m = 0;
        float ix1 = sbox[i][0], iy1 = sbox[i][1];
        float ix2 = sbox[i][2], iy2 = sbox[i][3];
        float icls = sbox[i][4], iar = sarea[i];
        int j0 = c * 32;
        #pragma unroll 8
        for (int jj = 0; jj < 32; ++jj) {
            int j = j0 + jj;
            if (j > i && j < KNMS && sbox[j][4] == icls) {
                float x1 = fmaxf(ix1, sbox[j][0]);
                float y1 = fmaxf(iy1, sbox[j][1]);
                float x2 = fminf(ix2, sbox[j][2]);
                float y2 = fminf(iy2, sbox[j][3]);
                float inter = fmaxf(x2 - x1, 0.f) * fmaxf(y2 - y1, 0.f);
                float uni = iar + sarea[j] - inter;
                if (inter / fmaxf(uni, 1e-9f) > IOU_THR) m |= (1u << jj);
            }
        }
        sup[i][c] = m;
    }
    __syncthreads();

    // exact greedy: keep &= ~sup[i] for each still-kept i, ascending
    if (t == 0) {
        unsigned k0 = keep0w[0], k1 = keep0w[1], k2 = keep0w[2], k3 = keep0w[3] & 0xFu;
        for (int i = 0; i < KNMS; ++i) {
            unsigned word = (i < 32) ? k0 : (i < 64) ? k1 : (i < 96) ? k2 : k3;
            unsigned bit = (word >> (i & 31)) & 1u;
            unsigned msk = (unsigned)(-(int)bit);
            k0 &= ~(sup[i][0] & msk);
            k1 &= ~(sup[i][1] & msk);
            k2 &= ~(sup[i][2] & msk);
            k3 &= ~(sup[i][3] & msk);
        }
        keepw[0] = k0; keepw[1] = k1; keepw[2] = k2; keepw[3] = k3;
    }
    __syncthreads();

    // write: sel [B,100,6] then keep [B,100] as 0/1 float
    float* out_sel = out;
    float* out_keep = out + (size_t)B * KNMS * 6;
    if (t < KNMS) {
        #pragma unroll
        for (int c = 0; c < 6; ++c)
            out_sel[((size_t)b * KNMS + t) * 6 + c] = sbox[t][c];
        out_keep[(size_t)b * KNMS + t] =
            ((keepw[t >> 5] >> (t & 31)) & 1u) ? 1.0f : 0.0f;
    }
}

// ============================================================
extern "C" void kernel_launch(void* const* d_in, const int* in_sizes, int n_in,
                              void* d_out, int out_size)
{
    const float* o13 = (const float*)d_in[0];
    const float* o26 = (const float*)d_in[1];
    const float* o52 = (const float*)d_in[2];
    const float* anc = (const float*)d_in[3];   // [3,3,2]
    const float* thr = (const float*)d_in[4];   // scalar

    int B = in_sizes[0] / (255 * CS13);
    if (B > BMAX) B = BMAX;
    float* out = (float*)d_out;

    stageA_kernel<<<B, 1024>>>(o13, o26, o52, anc, thr, B);
    stageB_kernel<<<B, 256>>>(out, B);
}

// round 8
// speedup vs baseline: 2.8305x; 1.1540x over previous
#include <cuda_runtime.h>
#include <cstdint>

// ---------------- problem constants ----------------
#define NTOT 10647          // 3*(13*13 + 26*26 + 52*52)
#define KNMS 100
#define BMAX 32
#define IOU_THR 0.3f

#define CS13 169
#define CS26 676
#define CS52 2704
#define BASE13 0
#define BASE26 507
#define BASE52 2535

__device__ __forceinline__ float sigmoidf_(float x) {
    return 1.0f / (1.0f + expf(-x));
}

// ============================================================
// ONE kernel, one block/image, 1024 threads:
//  1. score (conf channel only) -> shared
//  2. exact top-100 radix select (warp-agg histogram, shuffle pick)
//  3. rank permutation (no sort): key rank = #greater, barrier-free
//  4. gather-decode 100 anchors, write straight to sorted slot
//  5. suppression-bitmask build + pipelined greedy NMS
//  sbox/sarea/sup alias the (dead) score buffer; srank reuses hist.
// ============================================================
__global__ void __launch_bounds__(1024)
detector_kernel(const float* __restrict__ o13, const float* __restrict__ o26,
                const float* __restrict__ o52, const float* __restrict__ anc,
                const float* __restrict__ thr_p, float* __restrict__ out, int B)
{
    const int b = blockIdx.x;
    const int tid = threadIdx.x;
    const int lane = tid & 31;

    __shared__ float pool[NTOT];                  // 42588 B (scores, later boxes)
    __shared__ unsigned long long s_keys[128];
    __shared__ unsigned hist[256];                // later reused as srank
    __shared__ unsigned keep0w[4], keepw[4];
    __shared__ unsigned sh_prefix;
    __shared__ int sh_k, sh_cnt, sh_min, sh_last;

    float* s_scores = pool;
    float* sbox     = pool;                        // [100*6], alias (post-selection)
    float* sarea    = pool + 600;                  // [100]
    unsigned* sup   = (unsigned*)(pool + 704);     // [100*4]
    unsigned* srank = hist;                        // [128]

    const float thr = *thr_p;

    // ---- 1. score pass: conf channel (a*85) of each anchor, coalesced ----
    {
        const float* base13 = o13 + (size_t)b * 255 * CS13;
        const float* base26 = o26 + (size_t)b * 255 * CS26;
        const float* base52 = o52 + (size_t)b * 255 * CS52;
        #pragma unroll
        for (int a = 0; a < 3; ++a) {
            const float* p13 = base13 + (size_t)a * 85 * CS13;
            const float* p26 = base26 + (size_t)a * 85 * CS26;
            const float* p52 = base52 + (size_t)a * 85 * CS52;
            for (int cell = tid; cell < CS13; cell += 1024) {
                float c = sigmoidf_(p13[cell]);
                s_scores[BASE13 + cell * 3 + a] = (c > thr) ? c : 0.0f;
            }
            for (int cell = tid; cell < CS26; cell += 1024) {
                float c = sigmoidf_(p26[cell]);
                s_scores[BASE26 + cell * 3 + a] = (c > thr) ? c : 0.0f;
            }
            for (int cell = tid; cell < CS52; cell += 1024) {
                float c = sigmoidf_(p52[cell]);
                s_scores[BASE52 + cell * 3 + a] = (c > thr) ? c : 0.0f;
            }
        }
    }
    if (tid == 0) { sh_prefix = 0u; sh_k = KNMS; }
    __syncthreads();

    // ---- 2. 4-pass radix select on float bits (all scores >= 0) ----
    for (int pass = 0; pass < 4; ++pass) {
        unsigned prefix = sh_prefix;
        int k = sh_k;
        int shift = 24 - 8 * pass;
        unsigned maskHigh = (pass == 0) ? 0u : (0xFFFFFFFFu << (shift + 8));
        if (tid < 256) hist[tid] = 0u;
        __syncthreads();

        // histogram with warp-aggregated atomics
        for (int base = 0; base < NTOT; base += 1024) {
            int n = base + tid;
            bool inb = (n < NTOT);
            unsigned bits = inb ? __float_as_uint(s_scores[n]) : 0u;
            bool active = inb && ((bits & maskHigh) == prefix);
            unsigned actmask = __ballot_sync(0xffffffffu, active);
            if (active) {
                unsigned bin = (bits >> shift) & 0xFF;
                unsigned peers = __match_any_sync(actmask, bin);
                if (lane == __ffs(peers) - 1)
                    atomicAdd(&hist[bin], (unsigned)__popc(peers));
            }
        }
        __syncthreads();

        // warp 0: shuffle suffix-scan bin pick (8 bins/lane)
        if (tid < 32) {
            unsigned c[8];
            int T = 0;
            #pragma unroll
            for (int r = 0; r < 8; ++r) { c[r] = hist[tid * 8 + r]; T += (int)c[r]; }
            int S = T;
            #pragma unroll
            for (int off = 1; off < 32; off <<= 1) {
                int v = __shfl_down_sync(0xffffffffu, S, off);
                if (tid + off < 32) S += v;
            }
            int Snext = __shfl_down_sync(0xffffffffu, S, 1);
            if (tid == 31) Snext = 0;
            if (S >= k && Snext < k) {
                int rem = Snext, chosen = 0;
                #pragma unroll
                for (int r = 7; r >= 0; --r) {
                    if (rem + (int)c[r] >= k) { chosen = r; break; }
                    rem += (int)c[r];
                }
                sh_prefix = prefix | ((unsigned)(tid * 8 + chosen) << shift);
                sh_k = k - rem;
            }
        }
        __syncthreads();
    }

    const unsigned Tbits = sh_prefix;
    const int k_eq = sh_k;

    // ---- collect strictly-greater (unordered slots) ----
    if (tid == 0) sh_cnt = 0;
    __syncthreads();
    for (int n = tid; n < NTOT; n += 1024) {
        unsigned bits = __float_as_uint(s_scores[n]);
        if (bits > Tbits) {
            int pos = atomicAdd(&sh_cnt, 1);
            s_keys[pos] = ((unsigned long long)bits << 32) | (unsigned)(~(unsigned)n);
        }
    }
    __syncthreads();
    const int cnt_gt = sh_cnt;

    // ---- append k_eq smallest-index ==T elements (stable tie-break) ----
    if (tid == 0) sh_last = -1;
    __syncthreads();
    for (int it = 0; it < k_eq; ++it) {
        if (tid == 0) sh_min = 0x7FFFFFFF;
        __syncthreads();
        int last = sh_last;
        for (int n = tid; n < NTOT; n += 1024) {
            if (__float_as_uint(s_scores[n]) == Tbits && n > last)
                atomicMin(&sh_min, n);
        }
        __syncthreads();
        if (tid == 0) {
            s_keys[cnt_gt + it] =
                ((unsigned long long)Tbits << 32) | (unsigned)(~(unsigned)sh_min);
            sh_last = sh_min;
        }
        __syncthreads();
    }
    if (tid >= KNMS && tid < 128) s_keys[tid] = 0ull;   // padding
    __syncthreads();    // s_scores is DEAD after this point; pool reusable

    // ---- 3. init srank/keep0w, then rank (8 slices x 16 keys each) ----
    if (tid < 128) srank[tid] = 0u;
    if (tid < 4) { keep0w[tid] = 0u; }
    __syncthreads();
    {
        int kidx = tid & 127;
        int slice = tid >> 7;                         // 0..7
        unsigned long long mykey = s_keys[kidx];
        int cnt = 0;
        int j0 = slice * 16;
        #pragma unroll
        for (int j = 0; j < 16; ++j)
            if (s_keys[j0 + j] > mykey) cnt++;
        if (cnt) atomicAdd(&srank[kidx], (unsigned)cnt);
    }
    __syncthreads();

    // ---- 4. gather + decode 100 anchors, write to sorted slot ----
    {
        int wid = tid >> 5;
        for (int box = wid; box < KNMS; box += 32) {
            unsigned long long key = s_keys[box];
            unsigned idx = ~(unsigned)(key & 0xFFFFFFFFu);
            int rank = (int)srank[box];                  // unique in [0,100)

            int S, cs, base; float strd; const float* in; const float* arow;
            if (idx < BASE26)      { S = 13; cs = CS13; base = BASE13; strd = 32.f; in = o13; arow = anc + 0; }
            else if (idx < BASE52) { S = 26; cs = CS26; base = BASE26; strd = 16.f; in = o26; arow = anc + 6; }
            else                   { S = 52; cs = CS52; base = BASE52; strd = 8.f;  in = o52; arow = anc + 12; }
            int m = (int)idx - base;
            int cell = m / 3, a = m - cell * 3;
            int y = cell / S, x = cell - y * S;
            const float* p = in + ((size_t)b * 255 + (size_t)a * 85) * cs + cell;

            float v0 = p[(size_t)lane * cs];
            float v1 = p[(size_t)(lane + 32) * cs];
            float v2 = (lane < 21) ? p[(size_t)(lane + 64) * cs] : 0.f;

            float ch0 = __shfl_sync(0xffffffffu, v0, 0);
            float ch1 = __shfl_sync(0xffffffffu, v0, 1);
            float ch2 = __shfl_sync(0xffffffffu, v0, 2);
            float ch3 = __shfl_sync(0xffffffffu, v0, 3);
            float ch4 = __shfl_sync(0xffffffffu, v0, 4);

            // class argmax (first-max wins)
            float bv = -3.402823466e+38f;
            int bi = 0x7FFFFFFF;
            if (lane >= 5)            { bv = v0; bi = lane - 5; }
            if (v1 > bv)              { bv = v1; bi = lane + 27; }
            if (lane < 21 && v2 > bv) { bv = v2; bi = lane + 59; }
            #pragma unroll
            for (int off = 16; off; off >>= 1) {
                float ov = __shfl_xor_sync(0xffffffffu, bv, off);
                int oi = __shfl_xor_sync(0xffffffffu, bi, off);
                if (ov > bv || (ov == bv && oi < bi)) { bv = ov; bi = oi; }
            }

            if (lane == 0) {
                float conf = sigmoidf_(ch0);
                float sx = sigmoidf_(ch1);
                float sy = sigmoidf_(ch2);
                float ww = expf(ch3) * arow[a * 2 + 0];
                float hh = expf(ch4) * arow[a * 2 + 1];
                float ox = ((float)x + sx) * strd;
                float oy = ((float)y + sy) * strd;
                float x1 = ox - 0.5f * ww, y1 = oy - 0.5f * hh;
                float x2 = ox + 0.5f * ww, y2 = oy + 0.5f * hh;
                sbox[rank * 6 + 0] = x1;
                sbox[rank * 6 + 1] = y1;
                sbox[rank * 6 + 2] = x2;
                sbox[rank * 6 + 3] = y2;
                sbox[rank * 6 + 4] = (float)bi;
                sbox[rank * 6 + 5] = conf;
                sarea[rank] = fmaxf(x2 - x1, 0.f) * fmaxf(y2 - y1, 0.f);
                if ((unsigned)(key >> 32) != 0u)
                    atomicOr(&keep0w[rank >> 5], 1u << (rank & 31));
            }
        }
    }
    __syncthreads();

    // ---- 5. suppression masks: sup[i*4+c] bit jj set if i suppresses j=c*32+jj ----
    for (int w = tid; w < KNMS * 4; w += 1024) {
        int i = w >> 2, c = w & 3;
        unsigned m = 0;
        float ix1 = sbox[i * 6 + 0], iy1 = sbox[i * 6 + 1];
        float ix2 = sbox[i * 6 + 2], iy2 = sbox[i * 6 + 3];
        float icls = sbox[i * 6 + 4], iar = sarea[i];
        int j0 = c * 32;
        #pragma unroll 8
        for (int jj = 0; jj < 32; ++jj) {
            int j = j0 + jj;
            if (j > i && j < KNMS && sbox[j * 6 + 4] == icls) {
                float x1 = fmaxf(ix1, sbox[j * 6 + 0]);
                float y1 = fmaxf(iy1, sbox[j * 6 + 1]);
                float x2 = fminf(ix2, sbox[j * 6 + 2]);
                float y2 = fminf(iy2, sbox[j * 6 + 3]);
                float inter = fmaxf(x2 - x1, 0.f) * fmaxf(y2 - y1, 0.f);
                float uni = iar + sarea[j] - inter;
                if (inter / fmaxf(uni, 1e-9f) > IOU_THR) m |= (1u << jj);
            }
        }
        sup[w] = m;
    }
    __syncthreads();

    // ---- greedy (thread 0), software-pipelined sup prefetch ----
    if (tid == 0) {
        unsigned k0 = keep0w[0], k1 = keep0w[1], k2 = keep0w[2], k3 = keep0w[3];
        unsigned n0 = sup[0], n1 = sup[1], n2 = sup[2], n3 = sup[3];
        for (int i = 0; i < KNMS; ++i) {
            unsigned s0 = n0, s1 = n1, s2 = n2, s3 = n3;
            if (i + 1 < KNMS) {
                n0 = sup[(i + 1) * 4 + 0];
                n1 = sup[(i + 1) * 4 + 1];
                n2 = sup[(i + 1) * 4 + 2];
                n3 = sup[(i + 1) * 4 + 3];
            }
            unsigned word = (i < 32) ? k0 : (i < 64) ? k1 : (i < 96) ? k2 : k3;
            unsigned msk = (unsigned)(-(int)((word >> (i & 31)) & 1u));
            k0 &= ~(s0 & msk);
            k1 &= ~(s1 & msk);
            k2 &= ~(s2 & msk);
            k3 &= ~(s3 & msk);
        }
        keepw[0] = k0; keepw[1] = k1; keepw[2] = k2; keepw[3] = k3;
    }
    __syncthreads();

    // ---- write: sel [B,100,6] then keep [B,100] as 0/1 float ----
    float* out_sel = out;
    float* out_keep = out + (size_t)B * KNMS * 6;
    if (tid < KNMS) {
        #pragma unroll
        for (int c = 0; c < 6; ++c)
            out_sel[((size_t)b * KNMS + tid) * 6 + c] = sbox[tid * 6 + c];
        out_keep[(size_t)b * KNMS + tid] =
            ((keepw[tid >> 5] >> (tid & 31)) & 1u) ? 1.0f : 0.0f;
    }
}

// ============================================================
extern "C" void kernel_launch(void* const* d_in, const int* in_sizes, int n_in,
                              void* d_out, int out_size)
{
    const float* o13 = (const float*)d_in[0];
    const float* o26 = (const float*)d_in[1];
    const float* o52 = (const float*)d_in[2];
    const float* anc = (const float*)d_in[3];   // [3,3,2]
    const float* thr = (const float*)d_in[4];   // scalar

    int B = in_sizes[0] / (255 * CS13);
    if (B > BMAX) B = BMAX;
    float* out = (float*)d_out;

    detector_kernel<<<B, 1024>>>(o13, o26, o52, anc, thr, out, B);
}